// round 6
// baseline (speedup 1.0000x reference)
#include <cuda_runtime.h>
#include <cuda_bf16.h>
#include <cstdint>

#define DINL __device__ __forceinline__

namespace {
constexpr int   kBatch   = 524288;
constexpr int   kRowsCTA = 64;                       // 4 warps x 16 rows
constexpr int   kNumTiles = kBatch / kRowsCTA;       // 8192
constexpr int   kThreads = 128;
constexpr float kDT = 0.01f;

// SMEM offsets in uint32 units (base 16B aligned)
constexpr int OFF_W2  = 0;      // B-frags of W2   [8 ks][16 nt][32 lane] uint2 -> 8192 u32
constexpr int OFF_W2T = 8192;   // B-frags of W2^T                        -> 8192 u32
constexpr int OFF_W1  = 16384;  // B-frags of W1 (K padded to 16) [16 nt][32] -> 1024 u32
constexpr int OFF_W1T = 17408;  // B-frags of W1^T [8 ks][32]              -> 512 u32
constexpr int OFF_B1  = 17920;  // f32[128]
constexpr int OFF_B2  = 18048;  // f32[128]
constexpr int OFF_W3  = 18176;  // f32[128]
constexpr int kSmemU32 = 18304; // 73216 bytes
}

DINL float tanh_fast(float x) { float r; asm("tanh.approx.f32 %0, %1;" : "=f"(r) : "f"(x)); return r; }

DINL uint32_t pack_bf2(float lo, float hi) {
    __nv_bfloat162 t = __floats2bfloat162_rn(lo, hi);   // .x = lo (low 16 bits)
    return *reinterpret_cast<uint32_t*>(&t);
}
DINL float2 unpack_bf2(uint32_t u) {
    __nv_bfloat162 t = *reinterpret_cast<__nv_bfloat162*>(&u);
    return make_float2(__bfloat162float(t.x), __bfloat162float(t.y));
}

// D = A(16x16 bf16, row) x B(16x8 bf16, col) + D, fp32 accum
DINL void mma16816(float c[4], uint32_t a0, uint32_t a1, uint32_t a2, uint32_t a3,
                   uint32_t b0, uint32_t b1) {
    asm volatile(
        "mma.sync.aligned.m16n8k16.row.col.f32.bf16.bf16.f32 "
        "{%0,%1,%2,%3}, {%4,%5,%6,%7}, {%8,%9}, {%0,%1,%2,%3};"
        : "+f"(c[0]), "+f"(c[1]), "+f"(c[2]), "+f"(c[3])
        : "r"(a0), "r"(a1), "r"(a2), "r"(a3), "r"(b0), "r"(b1));
}

// -----------------------------------------------------------------------------
// grad_eval: dz = dH/dz for 16 rows per warp. State s[4] is the C-fragment of
// the z tile (rows g,g+8 / cols c0,c0+1 with g=lane>>2, c0=(lane&3)*2).
// Output d[4] is the C-fragment of dz (same layout).
// -----------------------------------------------------------------------------
DINL void grad_eval(const uint2* __restrict__ w2f,  const uint2* __restrict__ w2tf,
                    const uint2* __restrict__ w1f,  const uint2* __restrict__ w1tf,
                    const float2* __restrict__ b1v, const float2* __restrict__ b2v,
                    const float2* __restrict__ w3v,
                    int lane, const float s[4], float d[4]) {
    const int tg = lane & 3;

    // ---- layer 1: pre1 = zpad @ W1  (K=16, upper 8 of A zero) ----
    uint32_t az0 = pack_bf2(s[0], s[1]);
    uint32_t az1 = pack_bf2(s[2], s[3]);
    float acc[64];
    uint32_t hf[8][4];   // h1 as A-fragments (K = 128)
    uint32_t gf[8][4];   // grad as A-fragments
#pragma unroll
    for (int nt = 0; nt < 16; nt++) {
        float* c = acc + nt * 4;
        c[0] = c[1] = c[2] = c[3] = 0.f;
        uint2 b = w1f[nt * 32 + lane];
        mma16816(c, az0, az1, 0u, 0u, b.x, b.y);
    }
    // h1 = tanh(pre1 + b1) -> A-frags
#pragma unroll
    for (int t = 0; t < 8; t++) {
#pragma unroll
        for (int h = 0; h < 2; h++) {
            int nt = 2 * t + h;
            float2 bb = b1v[nt * 4 + tg];
            float* c = acc + nt * 4;
            hf[t][2*h+0] = pack_bf2(tanh_fast(c[0] + bb.x), tanh_fast(c[1] + bb.y));
            hf[t][2*h+1] = pack_bf2(tanh_fast(c[2] + bb.x), tanh_fast(c[3] + bb.y));
        }
    }

    // ---- layer 2: pre2 = h1 @ W2 ----
#pragma unroll
    for (int nt = 0; nt < 16; nt++) {
        float* c = acc + nt * 4;
        c[0] = c[1] = c[2] = c[3] = 0.f;
#pragma unroll
        for (int ks = 0; ks < 8; ks++) {
            uint2 b = w2f[(ks * 16 + nt) * 32 + lane];
            mma16816(c, hf[ks][0], hf[ks][1], hf[ks][2], hf[ks][3], b.x, b.y);
        }
    }
    // dpre2 = w3 * (1 - tanh(pre2 + b2)^2) -> A-frags
#pragma unroll
    for (int t = 0; t < 8; t++) {
#pragma unroll
        for (int h = 0; h < 2; h++) {
            int nt = 2 * t + h;
            float2 bb = b2v[nt * 4 + tg];
            float2 ww = w3v[nt * 4 + tg];
            float* c = acc + nt * 4;
            float t0 = tanh_fast(c[0] + bb.x), t1 = tanh_fast(c[1] + bb.y);
            float t2 = tanh_fast(c[2] + bb.x), t3 = tanh_fast(c[3] + bb.y);
            gf[t][2*h+0] = pack_bf2(ww.x * (1.f - t0*t0), ww.y * (1.f - t1*t1));
            gf[t][2*h+1] = pack_bf2(ww.x * (1.f - t2*t2), ww.y * (1.f - t3*t3));
        }
    }

    // ---- backward hidden: dh1 = dpre2 @ W2^T ----
#pragma unroll
    for (int nt = 0; nt < 16; nt++) {
        float* c = acc + nt * 4;
        c[0] = c[1] = c[2] = c[3] = 0.f;
#pragma unroll
        for (int ks = 0; ks < 8; ks++) {
            uint2 b = w2tf[(ks * 16 + nt) * 32 + lane];
            mma16816(c, gf[ks][0], gf[ks][1], gf[ks][2], gf[ks][3], b.x, b.y);
        }
    }
    // dpre1 = dh1 * (1 - h1^2) -> A-frags (overwrite gf)
#pragma unroll
    for (int t = 0; t < 8; t++) {
#pragma unroll
        for (int h = 0; h < 2; h++) {
            int nt = 2 * t + h;
            float* c = acc + nt * 4;
            float2 h01 = unpack_bf2(hf[t][2*h+0]);
            float2 h23 = unpack_bf2(hf[t][2*h+1]);
            gf[t][2*h+0] = pack_bf2(c[0] * (1.f - h01.x*h01.x), c[1] * (1.f - h01.y*h01.y));
            gf[t][2*h+1] = pack_bf2(c[2] * (1.f - h23.x*h23.x), c[3] * (1.f - h23.y*h23.y));
        }
    }

    // ---- dz = dpre1 @ W1^T (N = 8) ----
    d[0] = d[1] = d[2] = d[3] = 0.f;
#pragma unroll
    for (int ks = 0; ks < 8; ks++) {
        uint2 b = w1tf[ks * 32 + lane];
        mma16816(d, gf[ks][0], gf[ks][1], gf[ks][2], gf[ks][3], b.x, b.y);
    }
}

// -----------------------------------------------------------------------------
__global__ void __launch_bounds__(kThreads)
symp_kernel(const float* __restrict__ z,  const float* __restrict__ W1,
            const float* __restrict__ b1, const float* __restrict__ W2,
            const float* __restrict__ b2, const float* __restrict__ W3,
            const float* __restrict__ b3, float* __restrict__ out) {
    extern __shared__ uint32_t sm[];
    const int tid = threadIdx.x;
    const int wid = tid >> 5, lane = tid & 31;

    // ---- build weight B-fragments in SMEM (once per persistent CTA) ----
    for (int idx = tid; idx < 8 * 16 * 32; idx += kThreads) {
        int ks = idx >> 9, nt = (idx >> 5) & 15, ln = idx & 31;
        int n  = nt * 8 + (ln >> 2);
        int kb = ks * 16 + (ln & 3) * 2;
        ((uint2*)(sm + OFF_W2))[idx] = make_uint2(
            pack_bf2(W2[kb * 128 + n],       W2[(kb + 1) * 128 + n]),
            pack_bf2(W2[(kb + 8) * 128 + n], W2[(kb + 9) * 128 + n]));
        ((uint2*)(sm + OFF_W2T))[idx] = make_uint2(
            pack_bf2(W2[n * 128 + kb],     W2[n * 128 + kb + 1]),
            pack_bf2(W2[n * 128 + kb + 8], W2[n * 128 + kb + 9]));
    }
    for (int idx = tid; idx < 16 * 32; idx += kThreads) {   // W1 pad K->16 (rows 8..15 zero)
        int nt = idx >> 5, ln = idx & 31;
        int n  = nt * 8 + (ln >> 2);
        int kb = (ln & 3) * 2;
        float v0 = (kb     < 8) ? W1[kb * 128 + n]       : 0.f;
        float v1 = (kb + 1 < 8) ? W1[(kb + 1) * 128 + n] : 0.f;
        ((uint2*)(sm + OFF_W1))[idx] = make_uint2(pack_bf2(v0, v1), pack_bf2(0.f, 0.f));
    }
    for (int idx = tid; idx < 8 * 32; idx += kThreads) {    // W1^T: B(k,n) = W1[n*128+k]
        int ks = idx >> 5, ln = idx & 31;
        int n  = ln >> 2;
        int kb = ks * 16 + (ln & 3) * 2;
        ((uint2*)(sm + OFF_W1T))[idx] = make_uint2(
            pack_bf2(W1[n * 128 + kb],     W1[n * 128 + kb + 1]),
            pack_bf2(W1[n * 128 + kb + 8], W1[n * 128 + kb + 9]));
    }
    ((float*)(sm + OFF_B1))[tid] = b1[tid];
    ((float*)(sm + OFF_B2))[tid] = b2[tid];
    ((float*)(sm + OFF_W3))[tid] = W3[tid];
    __syncthreads();

    const uint2*  w2f  = (const uint2*)(sm + OFF_W2);
    const uint2*  w2tf = (const uint2*)(sm + OFF_W2T);
    const uint2*  w1f  = (const uint2*)(sm + OFF_W1);
    const uint2*  w1tf = (const uint2*)(sm + OFF_W1T);
    const float2* b1v  = (const float2*)(sm + OFF_B1);
    const float2* b2v  = (const float2*)(sm + OFF_B2);
    const float2* w3v  = (const float2*)(sm + OFF_W3);
    (void)b3;  // constant offset: no effect on gradient

    const int gp = lane >> 2, tg = lane & 3;

    for (int t = blockIdx.x; t < kNumTiles; t += gridDim.x) {
        const int row0 = t * kRowsCTA + wid * 16;
        const float* zp = z + (size_t)(row0 + gp) * 8 + tg * 2;
        float s[4];
        {
            float2 v0 = *(const float2*)zp;          // row g
            float2 v1 = *(const float2*)(zp + 64);   // row g+8 (8 rows * 8 floats)
            s[0] = v0.x; s[1] = v0.y; s[2] = v1.x; s[3] = v1.y;
        }
        float d[4], dsw[4];
        // 4 grad evals: (eval, update) x 4 == 2 leapfrog steps
#pragma unroll 1
        for (int it = 0; it < 4; it++) {
            grad_eval(w2f, w2tf, w1f, w1tf, b1v, b2v, w3v, lane, s, d);
#pragma unroll
            for (int i = 0; i < 4; i++) dsw[i] = __shfl_xor_sync(0xffffffffu, d[i], 2);
            if ((it & 1) == 0) {
                if (tg < 2) {               // q cols: q += dt * dHdp
#pragma unroll
                    for (int i = 0; i < 4; i++) s[i] += kDT * dsw[i];
                } else {                    // p cols: p -= dt/2 * dHdq
#pragma unroll
                    for (int i = 0; i < 4; i++) s[i] -= 0.5f * kDT * dsw[i];
                }
            } else {
                if (tg >= 2) {              // p cols: p = p_half - dt/2 * dHdq
#pragma unroll
                    for (int i = 0; i < 4; i++) s[i] -= 0.5f * kDT * dsw[i];
                }
            }
        }
        float* op = out + (size_t)(row0 + gp) * 8 + tg * 2;
        *(float2*)op        = make_float2(s[0], s[1]);
        *(float2*)(op + 64) = make_float2(s[2], s[3]);
    }
}

extern "C" void kernel_launch(void* const* d_in, const int* in_sizes, int n_in,
                              void* d_out, int out_size) {
    const float* z  = (const float*)d_in[0];
    const float* W1 = (const float*)d_in[1];
    const float* b1 = (const float*)d_in[2];
    const float* W2 = (const float*)d_in[3];
    const float* b2 = (const float*)d_in[4];
    const float* W3 = (const float*)d_in[5];
    const float* b3 = (const float*)d_in[6];
    constexpr int kSmemBytes = kSmemU32 * 4;
    cudaFuncSetAttribute(symp_kernel, cudaFuncAttributeMaxDynamicSharedMemorySize, kSmemBytes);
    int grid = 304;                       // ~2 persistent CTAs / SM
    if (grid > kNumTiles) grid = kNumTiles;
    symp_kernel<<<grid, kThreads, kSmemBytes>>>(z, W1, b1, W2, b2, W3, b3, (float*)d_out);
    (void)in_sizes; (void)n_in; (void)out_size;
}